// round 14
// baseline (speedup 1.0000x reference)
#include <cuda_runtime.h>
#include <cuda_fp16.h>
#include <math.h>
#include <stdint.h>

#define NNODES 50000
#define NEDGES 800000
#define ETOT   (NNODES + NEDGES)
#define INS    512
#define HIDS   256
#define OUTS   128

// ---------------- device scratch ----------------
__device__ __align__(256) __half g_xh  [(size_t)NNODES * INS];
__device__ __align__(256) __half g_w1h [HIDS * INS];
__device__ __align__(256) __half g_w2h [OUTS * HIDS];
__device__ __align__(256) __half g_h1h [(size_t)NNODES * HIDS];
__device__ __align__(256) __half g_h1ah[(size_t)NNODES * HIDS];
__device__ __align__(256) __half g_h2h [(size_t)NNODES * OUTS];
__device__ float g_es1[NNODES];
__device__ float g_ed1[NNODES];
__device__ float g_es2[NNODES];
__device__ float g_ed2[NNODES];
__device__ int   g_counts[NNODES];          // indegree (no self-loop)
__device__ int   g_offsets[NNODES + 1];
__device__ int   g_cursor[NNODES];
__device__ int   g_esorted[ETOT];

__device__ __forceinline__ uint32_t smem_u32(const void* p) {
    return (uint32_t)__cvta_generic_to_shared(p);
}

__device__ __forceinline__ uint2 cvt4(float4 v) {
    __half2 a = __floats2half2_rn(v.x, v.y);
    __half2 b = __floats2half2_rn(v.z, v.w);
    return make_uint2(*(uint32_t*)&a, *(uint32_t*)&b);
}

// ---------------- 1: zero counts (must precede k_prep's count atomics) ----------------
__global__ void k_init0() {
    int i = blockIdx.x * blockDim.x + threadIdx.x;
    if (i < NNODES) g_counts[i] = 0;
}

// ---------------- 2: fused convert x/W1/W2 + degree count ----------------
// block ranges: [0,25000) x | [25000,25160) W | [25160,28285) count
__global__ void k_prep(const float4* __restrict__ x,
                       const float4* __restrict__ W1, const float4* __restrict__ W2,
                       const int* __restrict__ dst)
{
    const int bid = blockIdx.x;
    const int tid = threadIdx.x;
    if (bid < 25000) {
        int i = bid * 256 + tid;                      // 6.4M float4 exactly
        reinterpret_cast<uint2*>(g_xh)[i] = cvt4(__ldg(&x[i]));
    } else if (bid < 25160) {
        int i = (bid - 25000) * 256 + tid;            // 40960 float4 exactly
        const int N1 = HIDS * INS / 4;
        if (i < N1)
            reinterpret_cast<uint2*>(g_w1h)[i] = cvt4(__ldg(&W1[i]));
        else
            reinterpret_cast<uint2*>(g_w2h)[i - N1] = cvt4(__ldg(&W2[i - N1]));
    } else {
        int e = (bid - 25160) * 256 + tid;
        if (e < NEDGES) atomicAdd(&g_counts[dst[e]], 1);
    }
}

// ---------------- 3: scan (+1 self-loop per node) + bucket init, one block ----------------
__global__ void k_scanbk() {
    __shared__ int part[1024];
    const int tid = threadIdx.x;
    const int per = (NNODES + 1023) / 1024;   // 49
    const int base = tid * per;
    int s = 0;
    for (int i = 0; i < per; i++) {
        int idx = base + i;
        if (idx < NNODES) s += g_counts[idx] + 1;      // +1 = self-loop
    }
    part[tid] = s;
    __syncthreads();
    for (int off = 1; off < 1024; off <<= 1) {
        int v = (tid >= off) ? part[tid - off] : 0;
        __syncthreads();
        part[tid] += v;
        __syncthreads();
    }
    int run = (tid == 0) ? 0 : part[tid - 1];
    for (int i = 0; i < per; i++) {
        int idx = base + i;
        if (idx < NNODES) {
            g_offsets[idx] = run;
            g_esorted[run] = idx;       // self-loop first in bucket
            g_cursor[idx]  = run + 1;
            run += g_counts[idx] + 1;
        }
    }
    if (tid == 1023) g_offsets[NNODES] = part[1023];
}

// ---------------- 5: scatter edges into buckets ----------------
__global__ void k_scatter(const int* __restrict__ src, const int* __restrict__ dst) {
    int e = blockIdx.x * blockDim.x + threadIdx.x;
    if (e < NEDGES) {
        int d = dst[e];
        int p = atomicAdd(&g_cursor[d], 1);
        g_esorted[p] = src[e];
    }
}

// ---------------- fp16 mma GEMM, warp tile 64x32, K-chunk 32, 4-stage cp.async ----------------
// C[m][n] = sum_k A[m][k]*W[n][k]; fp16 in/out, fp32 accumulate.
// es/ed written FULLY by this kernel via SMEM reduction (no global atomics).

__device__ __forceinline__ void ldsm_x4(uint32_t* r, uint32_t addr) {
    asm volatile("ldmatrix.sync.aligned.m8n8.x4.shared.b16 {%0,%1,%2,%3}, [%4];"
                 : "=r"(r[0]), "=r"(r[1]), "=r"(r[2]), "=r"(r[3]) : "r"(addr));
}

__device__ __forceinline__ void mma_f16(float* d, const uint32_t* a,
                                        uint32_t b0, uint32_t b1) {
    asm volatile(
        "mma.sync.aligned.m16n8k16.row.col.f32.f16.f16.f32 "
        "{%0,%1,%2,%3}, {%4,%5,%6,%7}, {%8,%9}, {%0,%1,%2,%3};"
        : "+f"(d[0]), "+f"(d[1]), "+f"(d[2]), "+f"(d[3])
        : "r"(a[0]), "r"(a[1]), "r"(a[2]), "r"(a[3]), "r"(b0), "r"(b1));
}

__device__ __forceinline__ void cp_async16(uint32_t dst, const void* src) {
    asm volatile("cp.async.cg.shared.global [%0], [%1], 16;" :: "r"(dst), "l"(src) : "memory");
}

template <int MT, int NT, int THREADS>
__global__ void __launch_bounds__(THREADS, 512 / THREADS)
k_hgemm(const __half* __restrict__ A, const __half* __restrict__ W,
        __half* __restrict__ C,
        const float* __restrict__ asrc, const float* __restrict__ adst,
        float* __restrict__ es, float* __restrict__ ed,
        int M, int K)
{
    constexpr int RB = MT + NT;             // rows per stage
    constexpr int SB = RB * 64;             // bytes per stage (64B = kt32 row)
    constexpr int STAGES = 4;
    constexpr int WN = NT / 32;             // warps along N
    constexpr int UPT = RB * 4 / THREADS;   // 16B units per thread per chunk

    extern __shared__ uint8_t sbuf[];
    __shared__ float sred[MT][2];           // per-row es/ed partial sums

    const int tid  = threadIdx.x;
    const int lane = tid & 31;
    const int warp = tid >> 5;
    const int warpM = warp / WN;
    const int warpN = warp % WN;
    const int m0 = blockIdx.x * MT;
    const uint32_t sb0 = smem_u32(sbuf);

    // ---- loader setup ----
    const __half* gsrc[UPT];
    uint32_t sdst[UPT];
#pragma unroll
    for (int j = 0; j < UPT; j++) {
        int ul  = tid + j * THREADS;
        int row = ul >> 2, u = ul & 3;
        const __half* p;
        if (row < MT) {
            int rg = m0 + row;
            if (rg >= M) rg = M - 1;        // clamp; never stored
            p = A + (size_t)rg * K;
        } else {
            p = W + (size_t)(row - MT) * K;
        }
        gsrc[j] = p + u * 8;
        uint32_t pu = (uint32_t)u ^ (((uint32_t)row >> 1) & 3);
        sdst[j] = (uint32_t)(row * 64) + (pu << 4);
    }

    // ---- ldmatrix offsets (ks=1 => offset XOR 32, applied before base add) ----
    uint32_t aOff[4], bOff[2];
    {
        int arow = warpM * 64 + (lane & 15);
        uint32_t pu = ((uint32_t)(lane >> 4)) ^ (((uint32_t)arow >> 1) & 3);
        uint32_t a0 = (uint32_t)(arow * 64) + (pu << 4);
#pragma unroll
        for (int mt = 0; mt < 4; mt++)
            aOff[mt] = a0 + (uint32_t)(mt * 16 * 64);

        int brow = MT + warpN * 32 + (lane & 7) + ((lane & 16) >> 1);
        uint32_t pub = ((uint32_t)((lane >> 3) & 1)) ^ (((uint32_t)brow >> 1) & 3);
        uint32_t b0a = (uint32_t)(brow * 64) + (pub << 4);
#pragma unroll
        for (int bq = 0; bq < 2; bq++)
            bOff[bq] = b0a + (uint32_t)(bq * 16 * 64);
    }

    // zero the reduction buffer while loads fly
    for (int i = tid; i < MT * 2; i += THREADS)
        reinterpret_cast<float*>(sred)[i] = 0.f;

    float acc[4][4][4];
#pragma unroll
    for (int i = 0; i < 4; i++)
#pragma unroll
        for (int j = 0; j < 4; j++)
#pragma unroll
            for (int q = 0; q < 4; q++) acc[i][j][q] = 0.f;

    const int KT = K >> 5;

    auto load_chunk = [&](int c) {
        const uint32_t so = sb0 + (uint32_t)((c & (STAGES - 1)) * SB);
        const int kof = c << 5;
#pragma unroll
        for (int j = 0; j < UPT; j++)
            cp_async16(so + sdst[j], gsrc[j] + kof);
    };

#pragma unroll
    for (int c = 0; c < STAGES - 1; c++) {
        load_chunk(c);
        asm volatile("cp.async.commit_group;" ::: "memory");
    }

    for (int c = 0; c < KT; c++) {
        asm volatile("cp.async.wait_group 2;" ::: "memory");
        __syncthreads();

        const uint32_t soff = (uint32_t)((c & (STAGES - 1)) * SB);
#pragma unroll
        for (int ks = 0; ks < 2; ks++) {
            const uint32_t kx = (uint32_t)(ks << 5);
            uint32_t a[4][4], b[2][4];
#pragma unroll
            for (int mt = 0; mt < 4; mt++)
                ldsm_x4(a[mt], sb0 + ((aOff[mt] + soff) ^ kx));
#pragma unroll
            for (int bq = 0; bq < 2; bq++)
                ldsm_x4(b[bq], sb0 + ((bOff[bq] + soff) ^ kx));
#pragma unroll
            for (int mt = 0; mt < 4; mt++) {
#pragma unroll
                for (int nt = 0; nt < 4; nt++) {
                    uint32_t b0 = b[nt >> 1][(nt & 1) << 1];
                    uint32_t b1 = b[nt >> 1][((nt & 1) << 1) + 1];
                    mma_f16(acc[mt][nt], a[mt], b0, b1);
                }
            }
        }

        if (c + STAGES - 1 < KT) load_chunk(c + STAGES - 1);
        asm volatile("cp.async.commit_group;" ::: "memory");
    }

    // ---- epilogue: store C (fp16) + SMEM-reduced a_src/a_dst dots ----
    const int g  = lane >> 2;
    const int tq = lane & 3;

    float as_v[4][2], ad_v[4][2];
#pragma unroll
    for (int nt = 0; nt < 4; nt++) {
        int cc = warpN * 32 + nt * 8 + tq * 2;
        float2 a2v = *reinterpret_cast<const float2*>(&asrc[cc]);
        float2 d2v = *reinterpret_cast<const float2*>(&adst[cc]);
        as_v[nt][0] = a2v.x; as_v[nt][1] = a2v.y;
        ad_v[nt][0] = d2v.x; ad_v[nt][1] = d2v.y;
    }

    __syncthreads();   // sred zero + mainloop complete everywhere

#pragma unroll
    for (int mt = 0; mt < 4; mt++) {
        int lr0 = warpM * 64 + mt * 16 + g;
        int r0 = m0 + lr0;
        int r1 = r0 + 8;
        float es0 = 0.f, ed0 = 0.f, es1v = 0.f, ed1v = 0.f;
#pragma unroll
        for (int nt = 0; nt < 4; nt++) {
            int cc = warpN * 32 + nt * 8 + tq * 2;
            float vx0 = acc[mt][nt][0], vy0 = acc[mt][nt][1];
            float vx1 = acc[mt][nt][2], vy1 = acc[mt][nt][3];
            es0  += vx0 * as_v[nt][0] + vy0 * as_v[nt][1];
            ed0  += vx0 * ad_v[nt][0] + vy0 * ad_v[nt][1];
            es1v += vx1 * as_v[nt][0] + vy1 * as_v[nt][1];
            ed1v += vx1 * ad_v[nt][0] + vy1 * ad_v[nt][1];
            if (r0 < M) {
                __half2 hv = __floats2half2_rn(vx0, vy0);
                *reinterpret_cast<uint32_t*>(&C[(size_t)r0 * NT + cc]) = *(uint32_t*)&hv;
            }
            if (r1 < M) {
                __half2 hv = __floats2half2_rn(vx1, vy1);
                *reinterpret_cast<uint32_t*>(&C[(size_t)r1 * NT + cc]) = *(uint32_t*)&hv;
            }
        }
#pragma unroll
        for (int off = 1; off <= 2; off <<= 1) {
            es0  += __shfl_xor_sync(0xffffffffu, es0,  off);
            ed0  += __shfl_xor_sync(0xffffffffu, ed0,  off);
            es1v += __shfl_xor_sync(0xffffffffu, es1v, off);
            ed1v += __shfl_xor_sync(0xffffffffu, ed1v, off);
        }
        if (tq == 0) {
            atomicAdd(&sred[lr0][0], es0);      atomicAdd(&sred[lr0][1], ed0);
            atomicAdd(&sred[lr0 + 8][0], es1v); atomicAdd(&sred[lr0 + 8][1], ed1v);
        }
    }

    __syncthreads();
    for (int i = tid; i < MT; i += THREADS) {
        int r = m0 + i;
        if (r < M) {
            es[r] = sred[i][0];
            ed[r] = sred[i][1];
        }
    }
}

// ---------------- warp-per-dst softmax + aggregation (fp16 h) ----------------
template <bool RELU>
__global__ void k_agg256(const __half* __restrict__ h,
                         const float* __restrict__ es, const float* __restrict__ ed,
                         const float* __restrict__ bias, __half* __restrict__ outh)
{
    int warp = (blockIdx.x * blockDim.x + threadIdx.x) >> 5;
    int lane = threadIdx.x & 31;
    if (warp >= NNODES) return;

    const int beg = g_offsets[warp];
    const int end = g_offsets[warp + 1];
    const float edst = ed[warp];

    float a[8];
#pragma unroll
    for (int q = 0; q < 8; q++) a[q] = 0.f;
    float sum = 0.f;

    int sNext = g_esorted[beg];
    for (int i = beg; i < end; i++) {
        int s = sNext;
        if (i + 1 < end) sNext = g_esorted[i + 1];
        float e = es[s] + edst;
        e = (e > 0.f) ? e : 0.2f * e;
        float p = __expf(e);
        sum += p;
        uint4 v = __ldg(reinterpret_cast<const uint4*>(h + (size_t)s * 256) + lane);
        const __half2* hp = reinterpret_cast<const __half2*>(&v);
#pragma unroll
        for (int q = 0; q < 4; q++) {
            float2 f = __half22float2(hp[q]);
            a[2 * q]     += p * f.x;
            a[2 * q + 1] += p * f.y;
        }
    }

    float inv = 1.f / sum;
    float4 bv0 = *reinterpret_cast<const float4*>(&bias[lane * 8]);
    float4 bv1 = *reinterpret_cast<const float4*>(&bias[lane * 8 + 4]);
    float bb[8] = {bv0.x, bv0.y, bv0.z, bv0.w, bv1.x, bv1.y, bv1.z, bv1.w};

    uint4 o;
    __half2* op = reinterpret_cast<__half2*>(&o);
#pragma unroll
    for (int q = 0; q < 4; q++) {
        float xv = a[2 * q] * inv + bb[2 * q];
        float yv = a[2 * q + 1] * inv + bb[2 * q + 1];
        if (RELU) { xv = fmaxf(xv, 0.f); yv = fmaxf(yv, 0.f); }
        op[q] = __floats2half2_rn(xv, yv);
    }
    *(reinterpret_cast<uint4*>(outh + (size_t)warp * 256) + lane) = o;
}

__global__ void k_agg128(const __half* __restrict__ h,
                         const float* __restrict__ es, const float* __restrict__ ed,
                         const float* __restrict__ bias, float* __restrict__ out)
{
    int warp = (blockIdx.x * blockDim.x + threadIdx.x) >> 5;
    int lane = threadIdx.x & 31;
    if (warp >= NNODES) return;

    const int beg = g_offsets[warp];
    const int end = g_offsets[warp + 1];
    const float edst = ed[warp];

    float a0 = 0.f, a1 = 0.f, a2 = 0.f, a3 = 0.f;
    float sum = 0.f;

    int sNext = g_esorted[beg];
    for (int i = beg; i < end; i++) {
        int s = sNext;
        if (i + 1 < end) sNext = g_esorted[i + 1];
        float e = es[s] + edst;
        e = (e > 0.f) ? e : 0.2f * e;
        float p = __expf(e);
        sum += p;
        uint2 v = __ldg(reinterpret_cast<const uint2*>(h + (size_t)s * 128) + lane);
        float2 f0 = __half22float2(*reinterpret_cast<const __half2*>(&v.x));
        float2 f1 = __half22float2(*reinterpret_cast<const __half2*>(&v.y));
        a0 += p * f0.x; a1 += p * f0.y;
        a2 += p * f1.x; a3 += p * f1.y;
    }

    float inv = 1.f / sum;
    float4 bv = *reinterpret_cast<const float4*>(&bias[lane * 4]);
    float4 o = make_float4(a0 * inv + bv.x, a1 * inv + bv.y,
                           a2 * inv + bv.z, a3 * inv + bv.w);
    *(reinterpret_cast<float4*>(out + (size_t)warp * 128) + lane) = o;
}

// ---------------- host launcher ----------------
extern "C" void kernel_launch(void* const* d_in, const int* in_sizes, int n_in,
                              void* d_out, int out_size)
{
    (void)in_sizes; (void)n_in; (void)out_size;
    const float* x    = (const float*)d_in[0];
    const int*   ei   = (const int*)  d_in[1];
    const float* W1   = (const float*)d_in[3];
    const float* a1s  = (const float*)d_in[4];
    const float* a1d  = (const float*)d_in[5];
    const float* b1   = (const float*)d_in[6];
    const float* W2   = (const float*)d_in[7];
    const float* a2s  = (const float*)d_in[8];
    const float* a2d  = (const float*)d_in[9];
    const float* b2   = (const float*)d_in[10];
    float* out = (float*)d_out;

    const int* src = ei;
    const int* dst = ei + NEDGES;

    __half *xh, *w1h, *w2h, *h1h, *h1ah, *h2h;
    float *es1, *ed1, *es2, *ed2;
    cudaGetSymbolAddress((void**)&xh,   g_xh);
    cudaGetSymbolAddress((void**)&w1h,  g_w1h);
    cudaGetSymbolAddress((void**)&w2h,  g_w2h);
    cudaGetSymbolAddress((void**)&h1h,  g_h1h);
    cudaGetSymbolAddress((void**)&h1ah, g_h1ah);
    cudaGetSymbolAddress((void**)&h2h,  g_h2h);
    cudaGetSymbolAddress((void**)&es1,  g_es1);
    cudaGetSymbolAddress((void**)&ed1,  g_ed1);
    cudaGetSymbolAddress((void**)&es2,  g_es2);
    cudaGetSymbolAddress((void**)&ed2,  g_ed2);

    const int aggBlocks = (NNODES * 32 + 255) / 256;
    constexpr int SMEM1 = 4 * (128 + HIDS) * 64;   // 98304
    constexpr int SMEM2 = 4 * (128 + OUTS) * 64;   // 65536
    cudaFuncSetAttribute((const void*)k_hgemm<128, HIDS, 512>,
                         cudaFuncAttributeMaxDynamicSharedMemorySize, SMEM1);
    cudaFuncSetAttribute((const void*)k_hgemm<128, OUTS, 256>,
                         cudaFuncAttributeMaxDynamicSharedMemorySize, SMEM2);

    // 1: zero counts
    k_init0<<<(NNODES + 255) / 256, 256>>>();

    // 2: fused convert + degree count
    k_prep<<<28285, 256>>>((const float4*)x, (const float4*)W1, (const float4*)W2, dst);

    // 3: scan + bucket init (merged, single block)
    k_scanbk<<<1, 1024>>>();

    // 4: GEMM layer 1  (profiler capture slot)
    k_hgemm<128, HIDS, 512><<<(NNODES + 127) / 128, 512, SMEM1>>>(
        xh, w1h, h1h, a1s, a1d, es1, ed1, NNODES, INS);

    // 5: scatter (completes CSR)
    k_scatter<<<(NEDGES + 255) / 256, 256>>>(src, dst);

    // 6: layer-1 softmax-aggregate (+ReLU), fp16 out
    k_agg256<true><<<aggBlocks, 256>>>(h1h, es1, ed1, b1, h1ah);

    // 7: GEMM layer 2
    k_hgemm<128, OUTS, 256><<<(NNODES + 127) / 128, 256, SMEM2>>>(
        h1ah, w2h, h2h, a2s, a2d, es2, ed2, NNODES, HIDS);

    // 8: layer-2 softmax-aggregate, fp32 out
    k_agg128<<<aggBlocks, 256>>>(h2h, es2, ed2, b2, out);
}

// round 17
// speedup vs baseline: 1.2594x; 1.2594x over previous
#include <cuda_runtime.h>
#include <cuda_fp16.h>
#include <math.h>
#include <stdint.h>

#define NNODES 50000
#define NEDGES 800000
#define ETOT   (NNODES + NEDGES)
#define INS    512
#define HIDS   256
#define OUTS   128

// ---------------- device scratch ----------------
__device__ __align__(256) __half g_xh  [(size_t)NNODES * INS];
__device__ __align__(256) __half g_w1h [HIDS * INS];
__device__ __align__(256) __half g_w2h [OUTS * HIDS];
__device__ __align__(256) __half g_h1h [(size_t)NNODES * HIDS];
__device__ __align__(256) __half g_h1ah[(size_t)NNODES * HIDS];
__device__ __align__(256) __half g_h2h [(size_t)NNODES * OUTS];
__device__ float g_es1[NNODES];
__device__ float g_ed1[NNODES];
__device__ float g_es2[NNODES];
__device__ float g_ed2[NNODES];
__device__ int   g_counts[NNODES];
__device__ int   g_offsets[NNODES + 1];
__device__ int   g_cursor[NNODES];
__device__ int   g_esorted[ETOT];

__device__ __forceinline__ uint32_t smem_u32(const void* p) {
    return (uint32_t)__cvta_generic_to_shared(p);
}

__device__ __forceinline__ uint2 cvt4(float4 v) {
    __half2 a = __floats2half2_rn(v.x, v.y);
    __half2 b = __floats2half2_rn(v.z, v.w);
    return make_uint2(*(uint32_t*)&a, *(uint32_t*)&b);
}

// ---------------- 1: init (counts=1 self-loop, zero e-arrays) ----------------
__global__ void k_init0() {
    int i = blockIdx.x * blockDim.x + threadIdx.x;
    if (i < NNODES) {
        g_counts[i] = 1;                 // self-loop pre-counted
        g_es1[i] = 0.f; g_ed1[i] = 0.f;
        g_es2[i] = 0.f; g_ed2[i] = 0.f;
    }
}

// ---------------- 2: fused convert x/W1/W2 + degree count ----------------
// block ranges: [0,25000) x | [25000,25160) W | [25160,28285) count
__global__ void k_prep(const float4* __restrict__ x,
                       const float4* __restrict__ W1, const float4* __restrict__ W2,
                       const int* __restrict__ dst)
{
    const int bid = blockIdx.x;
    const int tid = threadIdx.x;
    if (bid < 25000) {
        int i = bid * 256 + tid;                      // 6.4M float4 exactly
        reinterpret_cast<uint2*>(g_xh)[i] = cvt4(__ldg(&x[i]));
    } else if (bid < 25160) {
        int i = (bid - 25000) * 256 + tid;            // 40960 float4 exactly
        const int N1 = HIDS * INS / 4;
        if (i < N1)
            reinterpret_cast<uint2*>(g_w1h)[i] = cvt4(__ldg(&W1[i]));
        else
            reinterpret_cast<uint2*>(g_w2h)[i - N1] = cvt4(__ldg(&W2[i - N1]));
    } else {
        int e = (bid - 25160) * 256 + tid;
        if (e < NEDGES) atomicAdd(&g_counts[dst[e]], 1);
    }
}

// ---------------- 3: exclusive scan (single block) ----------------
__global__ void k_scan() {
    __shared__ int part[1024];
    const int tid = threadIdx.x;
    const int per = (NNODES + 1023) / 1024;
    const int base = tid * per;
    int s = 0;
    for (int i = 0; i < per; i++) {
        int idx = base + i;
        if (idx < NNODES) s += g_counts[idx];
    }
    part[tid] = s;
    __syncthreads();
    for (int off = 1; off < 1024; off <<= 1) {
        int v = (tid >= off) ? part[tid - off] : 0;
        __syncthreads();
        part[tid] += v;
        __syncthreads();
    }
    int run = (tid == 0) ? 0 : part[tid - 1];
    for (int i = 0; i < per; i++) {
        int idx = base + i;
        if (idx < NNODES) {
            g_offsets[idx] = run;
            run += g_counts[idx];
        }
    }
    if (tid == 1023) g_offsets[NNODES] = part[1023];
}

// ---------------- 5: bucket init (multi-block; parallel scattered stores) ----------------
__global__ void k_init_buckets() {
    int i = blockIdx.x * blockDim.x + threadIdx.x;
    if (i < NNODES) {
        int o = g_offsets[i];
        g_esorted[o] = i;               // self-loop first in bucket
        g_cursor[i]  = o + 1;
    }
}

// ---------------- 6: scatter edges into buckets ----------------
__global__ void k_scatter(const int* __restrict__ src, const int* __restrict__ dst) {
    int e = blockIdx.x * blockDim.x + threadIdx.x;
    if (e < NEDGES) {
        int d = dst[e];
        int p = atomicAdd(&g_cursor[d], 1);
        g_esorted[p] = src[e];
    }
}

// ---------------- fp16 mma GEMM, N-slab partitioned, 2 CTAs/SM ----------------
// C[m][n0+n] = sum_k A[m][k]*W[n0+n][k]; fp16 in/out, fp32 accumulate.
// Fused partial es/ed dots via global atomicAdd (cross-slab accumulation).
// MT=128 rows, NTILE=128 cols per CTA, NTOT = full output width.

__device__ __forceinline__ void ldsm_x4(uint32_t* r, uint32_t addr) {
    asm volatile("ldmatrix.sync.aligned.m8n8.x4.shared.b16 {%0,%1,%2,%3}, [%4];"
                 : "=r"(r[0]), "=r"(r[1]), "=r"(r[2]), "=r"(r[3]) : "r"(addr));
}

__device__ __forceinline__ void mma_f16(float* d, const uint32_t* a,
                                        uint32_t b0, uint32_t b1) {
    asm volatile(
        "mma.sync.aligned.m16n8k16.row.col.f32.f16.f16.f32 "
        "{%0,%1,%2,%3}, {%4,%5,%6,%7}, {%8,%9}, {%0,%1,%2,%3};"
        : "+f"(d[0]), "+f"(d[1]), "+f"(d[2]), "+f"(d[3])
        : "r"(a[0]), "r"(a[1]), "r"(a[2]), "r"(a[3]), "r"(b0), "r"(b1));
}

__device__ __forceinline__ void cp_async16(uint32_t dst, const void* src) {
    asm volatile("cp.async.cg.shared.global [%0], [%1], 16;" :: "r"(dst), "l"(src) : "memory");
}

template <int MT, int NTILE, int NTOT, int THREADS>
__global__ void __launch_bounds__(THREADS, 2)
k_hgemm(const __half* __restrict__ A, const __half* __restrict__ W,
        __half* __restrict__ C,
        const float* __restrict__ asrc, const float* __restrict__ adst,
        float* __restrict__ es, float* __restrict__ ed,
        int M, int K)
{
    constexpr int RB = MT + NTILE;          // 256 rows per stage
    constexpr int SB = RB * 64;             // 16 KB per stage (64B = kt32 row)
    constexpr int STAGES = 4;
    constexpr int WN = NTILE / 32;          // warps along N
    constexpr int UPT = RB * 4 / THREADS;   // 16B units per thread per chunk

    extern __shared__ uint8_t sbuf[];

    const int tid  = threadIdx.x;
    const int lane = tid & 31;
    const int warp = tid >> 5;
    const int warpM = warp / WN;
    const int warpN = warp % WN;
    const int m0 = blockIdx.x * MT;
    const int n0 = blockIdx.y * NTILE;
    const uint32_t sb0 = smem_u32(sbuf);

    // ---- loader setup ----
    const __half* gsrc[UPT];
    uint32_t sdst[UPT];
#pragma unroll
    for (int j = 0; j < UPT; j++) {
        int ul  = tid + j * THREADS;
        int row = ul >> 2, u = ul & 3;
        const __half* p;
        if (row < MT) {
            int rg = m0 + row;
            if (rg >= M) rg = M - 1;        // clamp; never stored
            p = A + (size_t)rg * K;
        } else {
            p = W + (size_t)(n0 + row - MT) * K;
        }
        gsrc[j] = p + u * 8;
        uint32_t pu = (uint32_t)u ^ (((uint32_t)row >> 1) & 3);
        sdst[j] = (uint32_t)(row * 64) + (pu << 4);
    }

    // ---- ldmatrix offsets (ks=1 => offset XOR 32, applied before base add) ----
    uint32_t aOff[4], bOff[2];
    {
        int arow = warpM * 64 + (lane & 15);
        uint32_t pu = ((uint32_t)(lane >> 4)) ^ (((uint32_t)arow >> 1) & 3);
        uint32_t a0 = (uint32_t)(arow * 64) + (pu << 4);
#pragma unroll
        for (int mt = 0; mt < 4; mt++)
            aOff[mt] = a0 + (uint32_t)(mt * 16 * 64);

        int brow = MT + warpN * 32 + (lane & 7) + ((lane & 16) >> 1);
        uint32_t pub = ((uint32_t)((lane >> 3) & 1)) ^ (((uint32_t)brow >> 1) & 3);
        uint32_t b0a = (uint32_t)(brow * 64) + (pub << 4);
#pragma unroll
        for (int bq = 0; bq < 2; bq++)
            bOff[bq] = b0a + (uint32_t)(bq * 16 * 64);
    }

    float acc[4][4][4];
#pragma unroll
    for (int i = 0; i < 4; i++)
#pragma unroll
        for (int j = 0; j < 4; j++)
#pragma unroll
            for (int q = 0; q < 4; q++) acc[i][j][q] = 0.f;

    const int KT = K >> 5;

    auto load_chunk = [&](int c) {
        const uint32_t so = sb0 + (uint32_t)((c & (STAGES - 1)) * SB);
        const int kof = c << 5;
#pragma unroll
        for (int j = 0; j < UPT; j++)
            cp_async16(so + sdst[j], gsrc[j] + kof);
    };

#pragma unroll
    for (int c = 0; c < STAGES - 1; c++) {
        load_chunk(c);
        asm volatile("cp.async.commit_group;" ::: "memory");
    }

    for (int c = 0; c < KT; c++) {
        asm volatile("cp.async.wait_group 2;" ::: "memory");
        __syncthreads();

        const uint32_t soff = (uint32_t)((c & (STAGES - 1)) * SB);
#pragma unroll
        for (int ks = 0; ks < 2; ks++) {
            const uint32_t kx = (uint32_t)(ks << 5);
            uint32_t a[4][4], b[2][4];
#pragma unroll
            for (int mt = 0; mt < 4; mt++)
                ldsm_x4(a[mt], sb0 + ((aOff[mt] + soff) ^ kx));
#pragma unroll
            for (int bq = 0; bq < 2; bq++)
                ldsm_x4(b[bq], sb0 + ((bOff[bq] + soff) ^ kx));
#pragma unroll
            for (int mt = 0; mt < 4; mt++) {
#pragma unroll
                for (int nt = 0; nt < 4; nt++) {
                    uint32_t b0 = b[nt >> 1][(nt & 1) << 1];
                    uint32_t b1 = b[nt >> 1][((nt & 1) << 1) + 1];
                    mma_f16(acc[mt][nt], a[mt], b0, b1);
                }
            }
        }

        if (c + STAGES - 1 < KT) load_chunk(c + STAGES - 1);
        asm volatile("cp.async.commit_group;" ::: "memory");
    }

    // ---- epilogue: store C (fp16) + fused partial a_src/a_dst dots ----
    const int g  = lane >> 2;
    const int tq = lane & 3;

    float as_v[4][2], ad_v[4][2];
#pragma unroll
    for (int nt = 0; nt < 4; nt++) {
        int cc = n0 + warpN * 32 + nt * 8 + tq * 2;
        float2 a2v = *reinterpret_cast<const float2*>(&asrc[cc]);
        float2 d2v = *reinterpret_cast<const float2*>(&adst[cc]);
        as_v[nt][0] = a2v.x; as_v[nt][1] = a2v.y;
        ad_v[nt][0] = d2v.x; ad_v[nt][1] = d2v.y;
    }

#pragma unroll
    for (int mt = 0; mt < 4; mt++) {
        int r0 = m0 + warpM * 64 + mt * 16 + g;
        int r1 = r0 + 8;
        float es0 = 0.f, ed0 = 0.f, es1v = 0.f, ed1v = 0.f;
#pragma unroll
        for (int nt = 0; nt < 4; nt++) {
            int cc = n0 + warpN * 32 + nt * 8 + tq * 2;
            if (r0 < M) {
                float vx = acc[mt][nt][0], vy = acc[mt][nt][1];
                __half2 hv = __floats2half2_rn(vx, vy);
                *reinterpret_cast<uint32_t*>(&C[(size_t)r0 * NTOT + cc]) = *(uint32_t*)&hv;
                es0 += vx * as_v[nt][0] + vy * as_v[nt][1];
                ed0 += vx * ad_v[nt][0] + vy * ad_v[nt][1];
            }
            if (r1 < M) {
                float vx = acc[mt][nt][2], vy = acc[mt][nt][3];
                __half2 hv = __floats2half2_rn(vx, vy);
                *reinterpret_cast<uint32_t*>(&C[(size_t)r1 * NTOT + cc]) = *(uint32_t*)&hv;
                es1v += vx * as_v[nt][0] + vy * as_v[nt][1];
                ed1v += vx * ad_v[nt][0] + vy * ad_v[nt][1];
            }
        }
#pragma unroll
        for (int off = 1; off <= 2; off <<= 1) {
            es0  += __shfl_xor_sync(0xffffffffu, es0,  off);
            ed0  += __shfl_xor_sync(0xffffffffu, ed0,  off);
            es1v += __shfl_xor_sync(0xffffffffu, es1v, off);
            ed1v += __shfl_xor_sync(0xffffffffu, ed1v, off);
        }
        if (tq == 0) {
            if (r0 < M) { atomicAdd(&es[r0], es0);  atomicAdd(&ed[r0], ed0); }
            if (r1 < M) { atomicAdd(&es[r1], es1v); atomicAdd(&ed[r1], ed1v); }
        }
    }
}

// ---------------- warp-per-dst softmax + aggregation (fp16 h) ----------------
template <bool RELU>
__global__ void k_agg256(const __half* __restrict__ h,
                         const float* __restrict__ es, const float* __restrict__ ed,
                         const float* __restrict__ bias, __half* __restrict__ outh)
{
    int warp = (blockIdx.x * blockDim.x + threadIdx.x) >> 5;
    int lane = threadIdx.x & 31;
    if (warp >= NNODES) return;

    const int beg = g_offsets[warp];
    const int end = g_offsets[warp + 1];
    const float edst = ed[warp];

    float a[8];
#pragma unroll
    for (int q = 0; q < 8; q++) a[q] = 0.f;
    float sum = 0.f;

    int sNext = g_esorted[beg];
    float eNext = __ldg(&es[sNext]);
    for (int i = beg; i < end; i++) {
        int s = sNext;
        float eS = eNext;
        if (i + 1 < end) {                // prefetch next index + logit
            sNext = g_esorted[i + 1];
            eNext = __ldg(&es[sNext]);
        }
        float e = eS + edst;
        e = (e > 0.f) ? e : 0.2f * e;
        float p = __expf(e);
        sum += p;
        uint4 v = __ldg(reinterpret_cast<const uint4*>(h + (size_t)s * 256) + lane);
        const __half2* hp = reinterpret_cast<const __half2*>(&v);
#pragma unroll
        for (int q = 0; q < 4; q++) {
            float2 f = __half22float2(hp[q]);
            a[2 * q]     += p * f.x;
            a[2 * q + 1] += p * f.y;
        }
    }

    float inv = 1.f / sum;
    float4 bv0 = *reinterpret_cast<const float4*>(&bias[lane * 8]);
    float4 bv1 = *reinterpret_cast<const float4*>(&bias[lane * 8 + 4]);
    float bb[8] = {bv0.x, bv0.y, bv0.z, bv0.w, bv1.x, bv1.y, bv1.z, bv1.w};

    uint4 o;
    __half2* op = reinterpret_cast<__half2*>(&o);
#pragma unroll
    for (int q = 0; q < 4; q++) {
        float xv = a[2 * q] * inv + bb[2 * q];
        float yv = a[2 * q + 1] * inv + bb[2 * q + 1];
        if (RELU) { xv = fmaxf(xv, 0.f); yv = fmaxf(yv, 0.f); }
        op[q] = __floats2half2_rn(xv, yv);
    }
    *(reinterpret_cast<uint4*>(outh + (size_t)warp * 256) + lane) = o;
}

__global__ void k_agg128(const __half* __restrict__ h,
                         const float* __restrict__ es, const float* __restrict__ ed,
                         const float* __restrict__ bias, float* __restrict__ out)
{
    int warp = (blockIdx.x * blockDim.x + threadIdx.x) >> 5;
    int lane = threadIdx.x & 31;
    if (warp >= NNODES) return;

    const int beg = g_offsets[warp];
    const int end = g_offsets[warp + 1];
    const float edst = ed[warp];

    float a0 = 0.f, a1 = 0.f, a2 = 0.f, a3 = 0.f;
    float sum = 0.f;

    int sNext = g_esorted[beg];
    float eNext = __ldg(&es[sNext]);
    for (int i = beg; i < end; i++) {
        int s = sNext;
        float eS = eNext;
        if (i + 1 < end) {
            sNext = g_esorted[i + 1];
            eNext = __ldg(&es[sNext]);
        }
        float e = eS + edst;
        e = (e > 0.f) ? e : 0.2f * e;
        float p = __expf(e);
        sum += p;
        uint2 v = __ldg(reinterpret_cast<const uint2*>(h + (size_t)s * 128) + lane);
        float2 f0 = __half22float2(*reinterpret_cast<const __half2*>(&v.x));
        float2 f1 = __half22float2(*reinterpret_cast<const __half2*>(&v.y));
        a0 += p * f0.x; a1 += p * f0.y;
        a2 += p * f1.x; a3 += p * f1.y;
    }

    float inv = 1.f / sum;
    float4 bv = *reinterpret_cast<const float4*>(&bias[lane * 4]);
    float4 o = make_float4(a0 * inv + bv.x, a1 * inv + bv.y,
                           a2 * inv + bv.z, a3 * inv + bv.w);
    *(reinterpret_cast<float4*>(out + (size_t)warp * 128) + lane) = o;
}

// ---------------- host launcher ----------------
extern "C" void kernel_launch(void* const* d_in, const int* in_sizes, int n_in,
                              void* d_out, int out_size)
{
    (void)in_sizes; (void)n_in; (void)out_size;
    const float* x    = (const float*)d_in[0];
    const int*   ei   = (const int*)  d_in[1];
    const float* W1   = (const float*)d_in[3];
    const float* a1s  = (const float*)d_in[4];
    const float* a1d  = (const float*)d_in[5];
    const float* b1   = (const float*)d_in[6];
    const float* W2   = (const float*)d_in[7];
    const float* a2s  = (const float*)d_in[8];
    const float* a2d  = (const float*)d_in[9];
    const float* b2   = (const float*)d_in[10];
    float* out = (float*)d_out;

    const int* src = ei;
    const int* dst = ei + NEDGES;

    __half *xh, *w1h, *w2h, *h1h, *h1ah, *h2h;
    float *es1, *ed1, *es2, *ed2;
    cudaGetSymbolAddress((void**)&xh,   g_xh);
    cudaGetSymbolAddress((void**)&w1h,  g_w1h);
    cudaGetSymbolAddress((void**)&w2h,  g_w2h);
    cudaGetSymbolAddress((void**)&h1h,  g_h1h);
    cudaGetSymbolAddress((void**)&h1ah, g_h1ah);
    cudaGetSymbolAddress((void**)&h2h,  g_h2h);
    cudaGetSymbolAddress((void**)&es1,  g_es1);
    cudaGetSymbolAddress((void**)&ed1,  g_ed1);
    cudaGetSymbolAddress((void**)&es2,  g_es2);
    cudaGetSymbolAddress((void**)&ed2,  g_ed2);

    const int aggBlocks = (NNODES * 32 + 255) / 256;
    const int mBlocks = (NNODES + 127) / 128;
    constexpr int SMEM = 4 * 256 * 64;   // 65536 B (both GEMMs)
    cudaFuncSetAttribute((const void*)k_hgemm<128, 128, HIDS, 256>,
                         cudaFuncAttributeMaxDynamicSharedMemorySize, SMEM);
    cudaFuncSetAttribute((const void*)k_hgemm<128, 128, OUTS, 256>,
                         cudaFuncAttributeMaxDynamicSharedMemorySize, SMEM);

    // 1: init counts + zero e-arrays
    k_init0<<<(NNODES + 255) / 256, 256>>>();

    // 2: fused convert + degree count
    k_prep<<<28285, 256>>>((const float4*)x, (const float4*)W1, (const float4*)W2, dst);

    // 3: scan
    k_scan<<<1, 1024>>>();

    // 4: GEMM layer 1, two N-slabs, 2 CTAs/SM  (profiler capture slot)
    k_hgemm<128, 128, HIDS, 256><<<dim3(mBlocks, HIDS / 128), 256, SMEM>>>(
        xh, w1h, h1h, a1s, a1d, es1, ed1, NNODES, INS);

    // 5-6: buckets + scatter (complete CSR)
    k_init_buckets<<<(NNODES + 255) / 256, 256>>>();
    k_scatter<<<(NEDGES + 255) / 256, 256>>>(src, dst);

    // 7: layer-1 softmax-aggregate (+ReLU), fp16 out
    k_agg256<true><<<aggBlocks, 256>>>(h1h, es1, ed1, b1, h1ah);

    // 8: GEMM layer 2
    k_hgemm<128, 128, OUTS, 256><<<dim3(mBlocks, 1), 256, SMEM>>>(
        h1ah, w2h, h2h, a2s, a2d, es2, ed2, NNODES, HIDS);

    // 9: layer-2 softmax-aggregate, fp32 out
    k_agg128<<<aggBlocks, 256>>>(h2h, es2, ed2, b2, out);
}